// round 1
// baseline (speedup 1.0000x reference)
#include <cuda_runtime.h>
#include <math.h>

#define T_TOK 4096
#define H_DIM 2048
#define F_DIM 1024
#define E_NUM 16
#define K_TOP 4

// ---------------- device scratch (static globals: the sanctioned scratch path) ----
__device__ int   d_cnt[E_NUM];
__device__ int   d_tok[E_NUM * T_TOK];                       // per-expert token lists
__device__ int   d_slot[T_TOK * K_TOP];                      // (t,k) -> global row in ybuf/act
__device__ float d_wk[T_TOK * K_TOP];                        // (t,k) -> routing weight
__device__ float d_act[(size_t)E_NUM * T_TOK * F_DIM];       // SwiGLU activations (256 MB)
__device__ float d_ybuf[(size_t)E_NUM * T_TOK * H_DIM];      // down-proj outputs (512 MB)
__device__ float d_logits_fallback[(size_t)T_TOK * E_NUM];   // in case out buffer lacks logits

// ---------------- init: reset expert counters --------------------------------------
__global__ void init_kernel() {
    if (threadIdx.x < E_NUM) d_cnt[threadIdx.x] = 0;
}

// ---------------- router: logits, top-4, renorm weights, build lists ---------------
__global__ void __launch_bounds__(256) router_kernel(const float* __restrict__ x,
                                                     const float* __restrict__ wg,
                                                     float* __restrict__ logits_out) {
    int t   = blockIdx.x;
    int tid = threadIdx.x;

    float acc[E_NUM];
#pragma unroll
    for (int e = 0; e < E_NUM; e++) acc[e] = 0.f;

    const float* xr = x + (size_t)t * H_DIM;
    for (int h = tid; h < H_DIM; h += 256) {
        float xv = xr[h];
        const float* wrow = wg + (size_t)h * E_NUM;
#pragma unroll
        for (int e = 0; e < E_NUM; e++) acc[e] += xv * wrow[e];
    }

    // warp reduce each of the 16 accumulators
#pragma unroll
    for (int e = 0; e < E_NUM; e++) {
#pragma unroll
        for (int o = 16; o > 0; o >>= 1)
            acc[e] += __shfl_down_sync(0xffffffffu, acc[e], o);
    }

    __shared__ float sred[8][E_NUM];
    __shared__ float logits[E_NUM];
    int warp = tid >> 5, lane = tid & 31;
    if (lane == 0) {
#pragma unroll
        for (int e = 0; e < E_NUM; e++) sred[warp][e] = acc[e];
    }
    __syncthreads();

    if (tid < E_NUM) {
        float v = 0.f;
#pragma unroll
        for (int w = 0; w < 8; w++) v += sred[w][tid];
        logits[tid] = v;
        logits_out[(size_t)t * E_NUM + tid] = v;
    }
    __syncthreads();

    if (tid == 0) {
        float l[E_NUM];
#pragma unroll
        for (int e = 0; e < E_NUM; e++) l[e] = logits[e];

        int   sel[K_TOP];
        float selv[K_TOP];
        bool  used[E_NUM];
#pragma unroll
        for (int e = 0; e < E_NUM; e++) used[e] = false;

#pragma unroll
        for (int k = 0; k < K_TOP; k++) {
            int best = -1; float bv = -1e30f;
            for (int e = 0; e < E_NUM; e++) {
                if (!used[e] && l[e] > bv) { bv = l[e]; best = e; }
            }
            used[best] = true;
            sel[k] = best; selv[k] = bv;
        }

        // renormalized top-k softmax == softmax over the selected logits
        float m = selv[0];
        float w[K_TOP], sum = 0.f;
#pragma unroll
        for (int k = 0; k < K_TOP; k++) { w[k] = expf(selv[k] - m); sum += w[k]; }
        float inv = 1.f / sum;

#pragma unroll
        for (int k = 0; k < K_TOP; k++) {
            int e = sel[k];
            int pos = atomicAdd(&d_cnt[e], 1);
            d_tok[e * T_TOK + pos] = t;
            d_slot[t * K_TOP + k]  = e * T_TOK + pos;
            d_wk[t * K_TOP + k]    = w[k] * inv;
        }
    }
}

// ---------------- fused gate+up GEMM + SwiGLU -------------------------------------
// C1 = Xe @ Wg[e], C2 = Xe @ Wu[e]; d_act = silu(C1) * C2. Tiles 64x64, K-tile 16.
__global__ void __launch_bounds__(256) gateup_kernel(const float* __restrict__ x,
                                                     const float* __restrict__ Wg,
                                                     const float* __restrict__ Wu) {
    int e = blockIdx.z;
    int n = d_cnt[e];
    int row0 = blockIdx.x * 64;
    if (row0 >= n) return;
    int col0 = blockIdx.y * 64;

    __shared__ float Xs[64][17];
    __shared__ float Gs[16][64];
    __shared__ float Us[16][64];
    __shared__ int   toks[64];

    int tid = threadIdx.x;
    if (tid < 64) {
        int r = row0 + tid;
        toks[tid] = (r < n) ? d_tok[e * T_TOK + r] : -1;
    }
    __syncthreads();

    const float* wgp = Wg + (size_t)e * H_DIM * F_DIM;
    const float* wup = Wu + (size_t)e * H_DIM * F_DIM;

    float acc1[4][4], acc2[4][4];
#pragma unroll
    for (int i = 0; i < 4; i++)
#pragma unroll
        for (int j = 0; j < 4; j++) { acc1[i][j] = 0.f; acc2[i][j] = 0.f; }

    int tx = tid & 15, ty = tid >> 4;
    int xr = tid >> 2, xk = (tid & 3) * 4;      // Xs loader: 64 rows x 16 k
    int br = tid >> 4, bc = (tid & 15) * 4;     // B loader: 16 k x 64 cols

    int tk = toks[xr];
    const float* xrow = (tk >= 0) ? (x + (size_t)tk * H_DIM) : nullptr;

    for (int k0 = 0; k0 < H_DIM; k0 += 16) {
        float4 xv = make_float4(0.f, 0.f, 0.f, 0.f);
        if (xrow) xv = *(const float4*)(xrow + k0 + xk);
        Xs[xr][xk + 0] = xv.x; Xs[xr][xk + 1] = xv.y;
        Xs[xr][xk + 2] = xv.z; Xs[xr][xk + 3] = xv.w;

        *(float4*)&Gs[br][bc] = *(const float4*)(wgp + (size_t)(k0 + br) * F_DIM + col0 + bc);
        *(float4*)&Us[br][bc] = *(const float4*)(wup + (size_t)(k0 + br) * F_DIM + col0 + bc);
        __syncthreads();

#pragma unroll
        for (int kk = 0; kk < 16; kk++) {
            float a0 = Xs[ty * 4 + 0][kk];
            float a1 = Xs[ty * 4 + 1][kk];
            float a2 = Xs[ty * 4 + 2][kk];
            float a3 = Xs[ty * 4 + 3][kk];
            float4 bg = *(float4*)&Gs[kk][tx * 4];
            float4 bu = *(float4*)&Us[kk][tx * 4];

            acc1[0][0] += a0 * bg.x; acc1[0][1] += a0 * bg.y; acc1[0][2] += a0 * bg.z; acc1[0][3] += a0 * bg.w;
            acc1[1][0] += a1 * bg.x; acc1[1][1] += a1 * bg.y; acc1[1][2] += a1 * bg.z; acc1[1][3] += a1 * bg.w;
            acc1[2][0] += a2 * bg.x; acc1[2][1] += a2 * bg.y; acc1[2][2] += a2 * bg.z; acc1[2][3] += a2 * bg.w;
            acc1[3][0] += a3 * bg.x; acc1[3][1] += a3 * bg.y; acc1[3][2] += a3 * bg.z; acc1[3][3] += a3 * bg.w;

            acc2[0][0] += a0 * bu.x; acc2[0][1] += a0 * bu.y; acc2[0][2] += a0 * bu.z; acc2[0][3] += a0 * bu.w;
            acc2[1][0] += a1 * bu.x; acc2[1][1] += a1 * bu.y; acc2[1][2] += a1 * bu.z; acc2[1][3] += a1 * bu.w;
            acc2[2][0] += a2 * bu.x; acc2[2][1] += a2 * bu.y; acc2[2][2] += a2 * bu.z; acc2[2][3] += a2 * bu.w;
            acc2[3][0] += a3 * bu.x; acc2[3][1] += a3 * bu.y; acc2[3][2] += a3 * bu.z; acc2[3][3] += a3 * bu.w;
        }
        __syncthreads();
    }

#pragma unroll
    for (int i = 0; i < 4; i++) {
        int r = row0 + ty * 4 + i;
        if (r < n) {
            float* dst = d_act + ((size_t)e * T_TOK + r) * F_DIM + col0 + tx * 4;
#pragma unroll
            for (int j = 0; j < 4; j++) {
                float g = acc1[i][j];
                float s = g / (1.f + expf(-g));   // silu
                dst[j] = s * acc2[i][j];
            }
        }
    }
}

// ---------------- down GEMM: ybuf = act @ Wd[e] ------------------------------------
__global__ void __launch_bounds__(256) down_kernel(const float* __restrict__ Wd) {
    int e = blockIdx.z;
    int n = d_cnt[e];
    int row0 = blockIdx.x * 64;
    if (row0 >= n) return;
    int col0 = blockIdx.y * 64;

    __shared__ float Xs[64][17];
    __shared__ float Bs[16][64];

    int tid = threadIdx.x;
    int tx = tid & 15, ty = tid >> 4;
    int xr = tid >> 2, xk = (tid & 3) * 4;
    int br = tid >> 4, bc = (tid & 15) * 4;

    const float* wdp = Wd + (size_t)e * F_DIM * H_DIM;
    const float* arow = (row0 + xr < n)
        ? (d_act + ((size_t)e * T_TOK + row0 + xr) * F_DIM) : nullptr;

    float acc[4][4];
#pragma unroll
    for (int i = 0; i < 4; i++)
#pragma unroll
        for (int j = 0; j < 4; j++) acc[i][j] = 0.f;

    for (int k0 = 0; k0 < F_DIM; k0 += 16) {
        float4 xv = make_float4(0.f, 0.f, 0.f, 0.f);
        if (arow) xv = *(const float4*)(arow + k0 + xk);
        Xs[xr][xk + 0] = xv.x; Xs[xr][xk + 1] = xv.y;
        Xs[xr][xk + 2] = xv.z; Xs[xr][xk + 3] = xv.w;

        *(float4*)&Bs[br][bc] = *(const float4*)(wdp + (size_t)(k0 + br) * H_DIM + col0 + bc);
        __syncthreads();

#pragma unroll
        for (int kk = 0; kk < 16; kk++) {
            float a0 = Xs[ty * 4 + 0][kk];
            float a1 = Xs[ty * 4 + 1][kk];
            float a2 = Xs[ty * 4 + 2][kk];
            float a3 = Xs[ty * 4 + 3][kk];
            float4 b = *(float4*)&Bs[kk][tx * 4];

            acc[0][0] += a0 * b.x; acc[0][1] += a0 * b.y; acc[0][2] += a0 * b.z; acc[0][3] += a0 * b.w;
            acc[1][0] += a1 * b.x; acc[1][1] += a1 * b.y; acc[1][2] += a1 * b.z; acc[1][3] += a1 * b.w;
            acc[2][0] += a2 * b.x; acc[2][1] += a2 * b.y; acc[2][2] += a2 * b.z; acc[2][3] += a2 * b.w;
            acc[3][0] += a3 * b.x; acc[3][1] += a3 * b.y; acc[3][2] += a3 * b.z; acc[3][3] += a3 * b.w;
        }
        __syncthreads();
    }

#pragma unroll
    for (int i = 0; i < 4; i++) {
        int r = row0 + ty * 4 + i;
        if (r < n) {
            float* dst = d_ybuf + ((size_t)e * T_TOK + r) * H_DIM + col0 + tx * 4;
#pragma unroll
            for (int j = 0; j < 4; j++) dst[j] = acc[i][j];
        }
    }
}

// ---------------- combine: out[t] = sum_k w[t,k] * ybuf[slot[t,k]] -----------------
__global__ void __launch_bounds__(256) combine_kernel(float* __restrict__ out) {
    int t   = blockIdx.x;
    int tid = threadIdx.x;

    __shared__ int   sl[K_TOP];
    __shared__ float sw[K_TOP];
    if (tid < K_TOP) {
        sl[tid] = d_slot[t * K_TOP + tid];
        sw[tid] = d_wk[t * K_TOP + tid];
    }
    __syncthreads();

    const float* y0 = d_ybuf + (size_t)sl[0] * H_DIM;
    const float* y1 = d_ybuf + (size_t)sl[1] * H_DIM;
    const float* y2 = d_ybuf + (size_t)sl[2] * H_DIM;
    const float* y3 = d_ybuf + (size_t)sl[3] * H_DIM;
    float w0 = sw[0], w1 = sw[1], w2 = sw[2], w3 = sw[3];

    float* op = out + (size_t)t * H_DIM;
    for (int h = tid * 4; h < H_DIM; h += 256 * 4) {
        float4 a = *(const float4*)(y0 + h);
        float4 b = *(const float4*)(y1 + h);
        float4 c = *(const float4*)(y2 + h);
        float4 d = *(const float4*)(y3 + h);
        float4 r;
        r.x = w0 * a.x + w1 * b.x + w2 * c.x + w3 * d.x;
        r.y = w0 * a.y + w1 * b.y + w2 * c.y + w3 * d.y;
        r.z = w0 * a.z + w1 * b.z + w2 * c.z + w3 * d.z;
        r.w = w0 * a.w + w1 * b.w + w2 * c.w + w3 * d.w;
        *(float4*)(op + h) = r;
    }
}

// ---------------- launch ------------------------------------------------------------
extern "C" void kernel_launch(void* const* d_in, const int* in_sizes, int n_in,
                              void* d_out, int out_size) {
    const float* x     = (const float*)d_in[0];   // [2,2048,2048]
    const float* wgate = (const float*)d_in[1];   // [2048,16]
    const float* Wg    = (const float*)d_in[2];   // [16,2048,1024]
    const float* Wu    = (const float*)d_in[3];   // [16,2048,1024]
    const float* Wd    = (const float*)d_in[4];   // [16,1024,2048]

    float* out = (float*)d_out;

    // second output (router_logits) follows the first in d_out, if space exists
    float* logits_out;
    if (out_size >= T_TOK * H_DIM + T_TOK * E_NUM) {
        logits_out = out + (size_t)T_TOK * H_DIM;
    } else {
        static float* fb = nullptr;
        if (!fb) cudaGetSymbolAddress((void**)&fb, d_logits_fallback);
        logits_out = fb;
    }

    init_kernel<<<1, 32>>>();
    router_kernel<<<T_TOK, 256>>>(x, wgate, logits_out);
    gateup_kernel<<<dim3(T_TOK / 64, F_DIM / 64, E_NUM), 256>>>(x, Wg, Wu);
    down_kernel<<<dim3(T_TOK / 64, H_DIM / 64, E_NUM), 256>>>(Wd);
    combine_kernel<<<T_TOK, 256>>>(out);
}